// round 1
// baseline (speedup 1.0000x reference)
#include <cuda_runtime.h>
#include <cuda_bf16.h>
#include <math.h>

#define NN 4096
#define IN_DIM 512
#define OUT_DIM 512
#define HEADS 4
#define DK 128

// ---------------- scratch ----------------
__device__ float g_Wh[NN * OUT_DIM];     // 8 MB
__device__ float g_slT[HEADS * NN];
__device__ float g_srT[HEADS * NN];
__device__ float g_MT[HEADS * NN];

__device__ __forceinline__ float lrelu(float x) { return x >= 0.f ? x : 0.2f * x; }

// ---------------- Kernel A: Wh = H @ W  (fp32 tiled GEMM) ----------------
// BM=128, BN=64, BK=16, 256 threads, 8x4 micro-tile.
__global__ void __launch_bounds__(256) gemm_kernel(const float* __restrict__ H,
                                                   const float* __restrict__ W,
                                                   float* __restrict__ Wh) {
    __shared__ float As[16][129];   // [k][m], padded
    __shared__ float Bs[16][64];    // [k][n]
    const int t = threadIdx.x;
    const int rb = blockIdx.y * 128;
    const int cb = blockIdx.x * 64;
    const int rg = t >> 4;      // 0..15 -> rows rg*8..rg*8+7
    const int cg = t & 15;      // 0..15 -> cols cg*4..cg*4+3

    float acc[8][4];
#pragma unroll
    for (int u = 0; u < 8; u++)
#pragma unroll
        for (int v = 0; v < 4; v++) acc[u][v] = 0.f;

    for (int kb = 0; kb < IN_DIM; kb += 16) {
#pragma unroll
        for (int i = 0; i < 8; i++) {
            int idx = t + i * 256;            // 2048 elems
            int m = idx >> 4, kk = idx & 15;
            As[kk][m] = H[(size_t)(rb + m) * IN_DIM + kb + kk];
        }
#pragma unroll
        for (int i = 0; i < 4; i++) {
            int idx = t + i * 256;            // 1024 elems
            int kk = idx >> 6, c = idx & 63;
            Bs[kk][c] = W[(size_t)(kb + kk) * OUT_DIM + cb + c];
        }
        __syncthreads();
#pragma unroll
        for (int kk = 0; kk < 16; kk++) {
            float a[8], b[4];
#pragma unroll
            for (int u = 0; u < 8; u++) a[u] = As[kk][rg * 8 + u];
#pragma unroll
            for (int v = 0; v < 4; v++) b[v] = Bs[kk][cg * 4 + v];
#pragma unroll
            for (int u = 0; u < 8; u++)
#pragma unroll
                for (int v = 0; v < 4; v++) acc[u][v] = fmaf(a[u], b[v], acc[u][v]);
        }
        __syncthreads();
    }
#pragma unroll
    for (int u = 0; u < 8; u++) {
        float4 o = make_float4(acc[u][0], acc[u][1], acc[u][2], acc[u][3]);
        *reinterpret_cast<float4*>(&Wh[(size_t)(rb + rg * 8 + u) * OUT_DIM + cb + cg * 4]) = o;
    }
}

// ---------------- Kernel B: sl/sr (transposed [h][N]) ----------------
__global__ void score_kernel(const float* __restrict__ Wh,
                             const float* __restrict__ al,
                             const float* __restrict__ ar,
                             float* __restrict__ slT, float* __restrict__ srT) {
    int i = blockIdx.x;
    int h = threadIdx.x >> 5;
    int lane = threadIdx.x & 31;
    float4 w = *reinterpret_cast<const float4*>(&Wh[(size_t)i * OUT_DIM + h * DK + lane * 4]);
    float4 l = *reinterpret_cast<const float4*>(&al[h * DK + lane * 4]);
    float4 r = *reinterpret_cast<const float4*>(&ar[h * DK + lane * 4]);
    float s1 = w.x * l.x + w.y * l.y + w.z * l.z + w.w * l.w;
    float s2 = w.x * r.x + w.y * r.y + w.z * r.z + w.w * r.w;
#pragma unroll
    for (int off = 16; off > 0; off >>= 1) {
        s1 += __shfl_xor_sync(0xFFFFFFFFu, s1, off);
        s2 += __shfl_xor_sync(0xFFFFFFFFu, s2, off);
    }
    if (lane == 0) {
        slT[h * NN + i] = s1;
        srT[h * NN + i] = s2;
    }
}

// ---------------- Kernel B2: per-row masked max of sr -> M ----------------
__global__ void __launch_bounds__(256) rowmax_kernel(const int* __restrict__ A,
                                                     const float* __restrict__ slT,
                                                     const float* __restrict__ srT,
                                                     float* __restrict__ MT) {
    int i = blockIdx.x;
    int t = threadIdx.x;
    const int* arow = A + (size_t)i * NN;
    float mx[HEADS];
#pragma unroll
    for (int h = 0; h < HEADS; h++) mx[h] = -INFINITY;
    for (int j = t; j < NN; j += 256) {
        bool allowed = (arow[j] > 0) || (j == i);
        if (allowed) {
#pragma unroll
            for (int h = 0; h < HEADS; h++) mx[h] = fmaxf(mx[h], srT[h * NN + j]);
        }
    }
    __shared__ float red[HEADS][256];
#pragma unroll
    for (int h = 0; h < HEADS; h++) red[h][t] = mx[h];
    __syncthreads();
    for (int s = 128; s > 0; s >>= 1) {
        if (t < s) {
#pragma unroll
            for (int h = 0; h < HEADS; h++)
                red[h][t] = fmaxf(red[h][t], red[h][t + s]);
        }
        __syncthreads();
    }
    if (t < HEADS) {
        float e = slT[t * NN + i] + red[t][0];
        MT[t * NN + i] = lrelu(e);
    }
}

// ---------------- Kernel C: fused masked softmax + aggregation ----------------
// grid (N/64, HEADS), 256 threads. CTA = 64 rows of one head. j-tiles of 64.
__global__ void __launch_bounds__(256) attn_kernel(const int* __restrict__ A,
                                                   const float* __restrict__ Wh,
                                                   const float* __restrict__ slT,
                                                   const float* __restrict__ srT,
                                                   const float* __restrict__ MT,
                                                   float* __restrict__ out) {
    __shared__ float sWh[64][DK];   // 32 KB
    __shared__ float sw[64][64];    // 16 KB
    __shared__ float ssl[64], sM[64];

    const int h = blockIdx.y;
    const int rb = blockIdx.x * 64;
    const int t = threadIdx.x;
    const int warp = t >> 5;
    const int lane = t & 31;

    if (t < 64) {
        ssl[t] = slT[h * NN + rb + t];
        sM[t]  = MT[h * NN + rb + t];
    }

    float4 acc[8];
    float lsum[8];
#pragma unroll
    for (int r = 0; r < 8; r++) {
        acc[r] = make_float4(0.f, 0.f, 0.f, 0.f);
        lsum[r] = 0.f;
    }

    const float4* Wh4 = reinterpret_cast<const float4*>(Wh);
    const int myc = t & 63;   // fixed column within tile for phase 1

    for (int jb = 0; jb < NN; jb += 64) {
        __syncthreads();   // previous phase-2 done; ssl/sM visible on iter 0

        // load Wh tile (64 x 128 fp32 as float4): 2048 float4 / 256 thr = 8 each
#pragma unroll
        for (int i = 0; i < 8; i++) {
            int idx = t + i * 256;        // = j*32 + d4
            int j = idx >> 5, d4 = idx & 31;
            reinterpret_cast<float4*>(sWh)[idx] =
                Wh4[(size_t)(jb + j) * (OUT_DIM / 4) + h * 32 + d4];
        }

        // phase 1: weights into sw (coalesced A reads)
        float srv = srT[h * NN + jb + myc];
#pragma unroll
        for (int k = 0; k < 16; k++) {
            int idx = t + k * 256;
            int r = idx >> 6;             // row in tile
            int gi = rb + r, gj = jb + myc;
            int a = A[(size_t)gi * NN + gj];
            bool allowed = (a > 0) | (gi == gj);
            float e = lrelu(ssl[r] + srv);
            float w = allowed ? __expf(e - sM[r]) : 0.f;
            sw[r][myc] = w;
        }
        __syncthreads();

        // phase 2: warp owns rows warp*8..+7, lane owns dims lane*4..+3
        const float4* sWh4 = reinterpret_cast<const float4*>(sWh);
#pragma unroll 4
        for (int j = 0; j < 64; j++) {
            float4 whv = sWh4[j * 32 + lane];
#pragma unroll
            for (int r = 0; r < 8; r++) {
                float wv = sw[warp * 8 + r][j];
                lsum[r] += wv;
                acc[r].x = fmaf(wv, whv.x, acc[r].x);
                acc[r].y = fmaf(wv, whv.y, acc[r].y);
                acc[r].z = fmaf(wv, whv.z, acc[r].z);
                acc[r].w = fmaf(wv, whv.w, acc[r].w);
            }
        }
    }

    // epilogue: normalize + ELU, coalesced float4 stores
#pragma unroll
    for (int r = 0; r < 8; r++) {
        int row = rb + warp * 8 + r;
        float inv = 1.f / lsum[r];
        float x0 = acc[r].x * inv, x1 = acc[r].y * inv,
              x2 = acc[r].z * inv, x3 = acc[r].w * inv;
        float4 o;
        o.x = x0 > 0.f ? x0 : (__expf(x0) - 1.f);
        o.y = x1 > 0.f ? x1 : (__expf(x1) - 1.f);
        o.z = x2 > 0.f ? x2 : (__expf(x2) - 1.f);
        o.w = x3 > 0.f ? x3 : (__expf(x3) - 1.f);
        reinterpret_cast<float4*>(out)[(size_t)row * (OUT_DIM / 4) + h * 32 + lane] = o;
    }
}

// ---------------- launch ----------------
extern "C" void kernel_launch(void* const* d_in, const int* in_sizes, int n_in,
                              void* d_out, int out_size) {
    const float* H  = (const float*)d_in[0];
    const int*   A  = (const int*)  d_in[1];
    const float* W  = (const float*)d_in[2];
    const float* al = (const float*)d_in[3];
    const float* ar = (const float*)d_in[4];
    float* out = (float*)d_out;

    float* Wh;  cudaGetSymbolAddress((void**)&Wh,  g_Wh);
    float* slT; cudaGetSymbolAddress((void**)&slT, g_slT);
    float* srT; cudaGetSymbolAddress((void**)&srT, g_srT);
    float* MT;  cudaGetSymbolAddress((void**)&MT,  g_MT);

    dim3 gA(OUT_DIM / 64, NN / 128);
    gemm_kernel<<<gA, 256>>>(H, W, Wh);

    score_kernel<<<NN, 128>>>(Wh, al, ar, slT, srT);

    rowmax_kernel<<<NN, 256>>>(A, slT, srT, MT);

    dim3 gC(NN / 64, HEADS);
    attn_kernel<<<gC, 256>>>(A, Wh, slT, srT, MT, out);
}

// round 3
// speedup vs baseline: 1.7368x; 1.7368x over previous
#include <cuda_runtime.h>
#include <cuda_bf16.h>
#include <math.h>
#include <stdint.h>

#define NN 4096
#define IN_DIM 512
#define OUT_DIM 512
#define HEADS 4
#define DK 128
#define KT 64                    // j-tile
#define PAD 68                   // padded row stride (floats) for conflict-free frags
#define TILE_WORDS (128 * PAD)   // one buffer plane (words)

// ---------------- scratch ----------------
__device__ float g_Wh[NN * OUT_DIM];      // 8 MB
__device__ float g_WhT[OUT_DIM * NN];     // 8 MB, [d' = h*128+d][j], tf32-rounded
__device__ float g_slT[HEADS * NN];
__device__ float g_srT[HEADS * NN];
__device__ float g_MT[HEADS * NN];

__device__ __forceinline__ float lrelu(float x) { return x >= 0.f ? x : 0.2f * x; }
__device__ __forceinline__ uint32_t f2tf32(float v) {
    uint32_t r;
    asm("cvt.rn.tf32.f32 %0, %1;" : "=r"(r) : "f"(v));
    return r;
}
__device__ __forceinline__ void mma1688(float* c, uint32_t a0, uint32_t a1,
                                        uint32_t a2, uint32_t a3,
                                        uint32_t b0, uint32_t b1) {
    asm volatile(
        "mma.sync.aligned.m16n8k8.row.col.f32.tf32.tf32.f32 "
        "{%0,%1,%2,%3}, {%4,%5,%6,%7}, {%8,%9}, {%0,%1,%2,%3};"
        : "+f"(c[0]), "+f"(c[1]), "+f"(c[2]), "+f"(c[3])
        : "r"(a0), "r"(a1), "r"(a2), "r"(a3), "r"(b0), "r"(b1));
}

// ---------------- Kernel A: Wh = H @ W  (fp32 tiled GEMM) ----------------
__global__ void __launch_bounds__(256) gemm_kernel(const float* __restrict__ H,
                                                   const float* __restrict__ W,
                                                   float* __restrict__ Wh) {
    __shared__ float As[16][129];
    __shared__ float Bs[16][64];
    const int t = threadIdx.x;
    const int rb = blockIdx.y * 128;
    const int cb = blockIdx.x * 64;
    const int rg = t >> 4;
    const int cg = t & 15;

    float acc[8][4];
#pragma unroll
    for (int u = 0; u < 8; u++)
#pragma unroll
        for (int v = 0; v < 4; v++) acc[u][v] = 0.f;

    for (int kb = 0; kb < IN_DIM; kb += 16) {
#pragma unroll
        for (int i = 0; i < 8; i++) {
            int idx = t + i * 256;
            int m = idx >> 4, kk = idx & 15;
            As[kk][m] = H[(size_t)(rb + m) * IN_DIM + kb + kk];
        }
#pragma unroll
        for (int i = 0; i < 4; i++) {
            int idx = t + i * 256;
            int kk = idx >> 6, c = idx & 63;
            Bs[kk][c] = W[(size_t)(kb + kk) * OUT_DIM + cb + c];
        }
        __syncthreads();
#pragma unroll
        for (int kk = 0; kk < 16; kk++) {
            float a[8], b[4];
#pragma unroll
            for (int u = 0; u < 8; u++) a[u] = As[kk][rg * 8 + u];
#pragma unroll
            for (int v = 0; v < 4; v++) b[v] = Bs[kk][cg * 4 + v];
#pragma unroll
            for (int u = 0; u < 8; u++)
#pragma unroll
                for (int v = 0; v < 4; v++) acc[u][v] = fmaf(a[u], b[v], acc[u][v]);
        }
        __syncthreads();
    }
#pragma unroll
    for (int u = 0; u < 8; u++) {
        float4 o = make_float4(acc[u][0], acc[u][1], acc[u][2], acc[u][3]);
        *reinterpret_cast<float4*>(&Wh[(size_t)(rb + rg * 8 + u) * OUT_DIM + cb + cg * 4]) = o;
    }
}

// ---------------- Kernel B: sl/sr (transposed [h][N]) ----------------
__global__ void score_kernel(const float* __restrict__ Wh,
                             const float* __restrict__ al,
                             const float* __restrict__ ar,
                             float* __restrict__ slT, float* __restrict__ srT) {
    int i = blockIdx.x;
    int h = threadIdx.x >> 5;
    int lane = threadIdx.x & 31;
    float4 w = *reinterpret_cast<const float4*>(&Wh[(size_t)i * OUT_DIM + h * DK + lane * 4]);
    float4 l = *reinterpret_cast<const float4*>(&al[h * DK + lane * 4]);
    float4 r = *reinterpret_cast<const float4*>(&ar[h * DK + lane * 4]);
    float s1 = w.x * l.x + w.y * l.y + w.z * l.z + w.w * l.w;
    float s2 = w.x * r.x + w.y * r.y + w.z * r.z + w.w * r.w;
#pragma unroll
    for (int off = 16; off > 0; off >>= 1) {
        s1 += __shfl_xor_sync(0xFFFFFFFFu, s1, off);
        s2 += __shfl_xor_sync(0xFFFFFFFFu, s2, off);
    }
    if (lane == 0) {
        slT[h * NN + i] = s1;
        srT[h * NN + i] = s2;
    }
}

// ---------------- Kernel B2: per-row masked max of sr -> M ----------------
__global__ void __launch_bounds__(256) rowmax_kernel(const int* __restrict__ A,
                                                     const float* __restrict__ slT,
                                                     const float* __restrict__ srT,
                                                     float* __restrict__ MT) {
    int i = blockIdx.x;
    int t = threadIdx.x;
    const int* arow = A + (size_t)i * NN;
    float mx[HEADS];
#pragma unroll
    for (int h = 0; h < HEADS; h++) mx[h] = -INFINITY;
    for (int j = t; j < NN; j += 256) {
        bool allowed = (arow[j] > 0) || (j == i);
        if (allowed) {
#pragma unroll
            for (int h = 0; h < HEADS; h++) mx[h] = fmaxf(mx[h], srT[h * NN + j]);
        }
    }
    __shared__ float red[HEADS][256];
#pragma unroll
    for (int h = 0; h < HEADS; h++) red[h][t] = mx[h];
    __syncthreads();
    for (int s = 128; s > 0; s >>= 1) {
        if (t < s) {
#pragma unroll
            for (int h = 0; h < HEADS; h++)
                red[h][t] = fmaxf(red[h][t], red[h][t + s]);
        }
        __syncthreads();
    }
    if (t < HEADS) {
        float e = slT[t * NN + i] + red[t][0];
        MT[t * NN + i] = lrelu(e);
    }
}

// ---------------- Kernel B3: WhT[d'][j] = tf32(Wh[j][d']) ----------------
__global__ void __launch_bounds__(256) transpose_kernel(const float* __restrict__ Wh,
                                                        float* __restrict__ WhT) {
    __shared__ float tile[32][33];
    int jb = blockIdx.x * 32, db = blockIdx.y * 32;
    int tx = threadIdx.x & 31, ty = threadIdx.x >> 5;
#pragma unroll
    for (int i = 0; i < 32; i += 8)
        tile[ty + i][tx] = Wh[(size_t)(jb + ty + i) * OUT_DIM + db + tx];
    __syncthreads();
#pragma unroll
    for (int i = 0; i < 32; i += 8) {
        float v = tile[tx][ty + i];
        WhT[(size_t)(db + ty + i) * NN + jb + tx] = __uint_as_float(f2tf32(v));
    }
}

// ---------------- Kernel C: mma.sync tf32 masked-softmax aggregation -------
// grid (32, HEADS), 256 threads (8 warps). CTA = 128 rows, one head.
// j tiles of 64, double-buffered smem, 1 sync/tile.
// Dynamic smem: [buf][ sw(128*PAD words tf32) | swh(128*PAD words fp32) ] x2
__global__ void __launch_bounds__(256) attn_kernel(const int* __restrict__ A,
                                                   const float* __restrict__ WhT,
                                                   const float* __restrict__ slT,
                                                   const float* __restrict__ srT,
                                                   const float* __restrict__ MT,
                                                   float* __restrict__ out) {
    extern __shared__ uint32_t dyn[];
    __shared__ float ssl[128], sMx[128];

    const int h = blockIdx.y;
    const int rb = blockIdx.x * 128;
    const int t = threadIdx.x;
    const int wid = t >> 5, lane = t & 31;
    const int g = lane >> 2, tig = lane & 3;

    if (t < 128) {
        ssl[t] = slT[h * NN + rb + t];
        sMx[t] = MT[h * NN + rb + t];
    }
    __syncthreads();

    float acc[16][4];
#pragma unroll
    for (int nt = 0; nt < 16; nt++)
#pragma unroll
        for (int v = 0; v < 4; v++) acc[nt][v] = 0.f;
    float ls0 = 0.f, ls1 = 0.f;   // row-sum partials (rows g, g+8 of warp tile)

    const int c1 = t & 63;        // phase-1 column
    const int r0 = t >> 6;        // phase-1 base row (stride 4)
    const int arow_a = (wid * 16 + g) * PAD;        // A-frag row base
    const int arow_b = arow_a + 8 * PAD;

    for (int jt = 0; jt < NN / KT; jt++) {
        const int jb = jt * KT;
        const int buf = jt & 1;
        uint32_t* sw = dyn + buf * 2 * TILE_WORDS;
        float* swh = reinterpret_cast<float*>(dyn + buf * 2 * TILE_WORDS + TILE_WORDS);

        // ---- fill phase: weights (tf32) + WhT tile ----
        float srv = srT[h * NN + jb + c1];
#pragma unroll
        for (int k = 0; k < 32; k++) {
            int r = r0 + k * 4;
            int gi = rb + r, gj = jb + c1;
            int a = A[(size_t)gi * NN + gj];
            float e = lrelu(ssl[r] + srv);
            float w = ((a > 0) | (gi == gj)) ? __expf(e - sMx[r]) : 0.f;
            sw[r * PAD + c1] = f2tf32(w);
        }
#pragma unroll
        for (int i = 0; i < 32; i++) {
            int idx = t + i * 256;
            int r = idx >> 6, cc = idx & 63;
            swh[r * PAD + cc] = WhT[(size_t)(h * DK + r) * NN + jb + cc];
        }
        __syncthreads();

        // ---- mma phase: 8 k-chunks of 8 ----
#pragma unroll 2
        for (int kc = 0; kc < 8; kc++) {
            const int k0 = kc * 8 + tig;
            uint32_t a0 = sw[arow_a + k0];
            uint32_t a2 = sw[arow_a + k0 + 4];
            uint32_t a1 = sw[arow_b + k0];
            uint32_t a3 = sw[arow_b + k0 + 4];
            ls0 += __uint_as_float(a0) + __uint_as_float(a2);
            ls1 += __uint_as_float(a1) + __uint_as_float(a3);
#pragma unroll
            for (int nt = 0; nt < 16; nt++) {
                uint32_t b0 = __float_as_uint(swh[(nt * 8 + g) * PAD + k0]);
                uint32_t b1 = __float_as_uint(swh[(nt * 8 + g) * PAD + k0 + 4]);
                mma1688(acc[nt], a0, a1, a2, a3, b0, b1);
            }
        }
        // next iteration fills the other buffer; 1 sync/tile is sufficient
    }

    // ---- reduce lsum across the quad (tig 0..3 hold disjoint k) ----
    ls0 += __shfl_xor_sync(0xFFFFFFFFu, ls0, 1);
    ls0 += __shfl_xor_sync(0xFFFFFFFFu, ls0, 2);
    ls1 += __shfl_xor_sync(0xFFFFFFFFu, ls1, 1);
    ls1 += __shfl_xor_sync(0xFFFFFFFFu, ls1, 2);
    float inv0 = 1.f / ls0, inv1 = 1.f / ls1;

    // ---- epilogue: normalize + ELU, float2 stores ----
    const int row0 = rb + wid * 16 + g;
    const int row1 = row0 + 8;
#pragma unroll
    for (int nt = 0; nt < 16; nt++) {
        int col = h * DK + nt * 8 + 2 * tig;
        float x0 = acc[nt][0] * inv0, x1 = acc[nt][1] * inv0;
        float y0 = acc[nt][2] * inv1, y1 = acc[nt][3] * inv1;
        float2 o0, o1;
        o0.x = x0 > 0.f ? x0 : (__expf(x0) - 1.f);
        o0.y = x1 > 0.f ? x1 : (__expf(x1) - 1.f);
        o1.x = y0 > 0.f ? y0 : (__expf(y0) - 1.f);
        o1.y = y1 > 0.f ? y1 : (__expf(y1) - 1.f);
        *reinterpret_cast<float2*>(&out[(size_t)row0 * OUT_DIM + col]) = o0;
        *reinterpret_cast<float2*>(&out[(size_t)row1 * OUT_DIM + col]) = o1;
    }
}

// ---------------- launch ----------------
extern "C" void kernel_launch(void* const* d_in, const int* in_sizes, int n_in,
                              void* d_out, int out_size) {
    const float* H  = (const float*)d_in[0];
    const int*   A  = (const int*)  d_in[1];
    const float* W  = (const float*)d_in[2];
    const float* al = (const float*)d_in[3];
    const float* ar = (const float*)d_in[4];
    float* out = (float*)d_out;

    float* Wh;  cudaGetSymbolAddress((void**)&Wh,  g_Wh);
    float* WhT; cudaGetSymbolAddress((void**)&WhT, g_WhT);
    float* slT; cudaGetSymbolAddress((void**)&slT, g_slT);
    float* srT; cudaGetSymbolAddress((void**)&srT, g_srT);
    float* MT;  cudaGetSymbolAddress((void**)&MT,  g_MT);

    dim3 gA(OUT_DIM / 64, NN / 128);
    gemm_kernel<<<gA, 256>>>(H, W, Wh);

    score_kernel<<<NN, 128>>>(Wh, al, ar, slT, srT);

    rowmax_kernel<<<NN, 256>>>(A, slT, srT, MT);

    dim3 gT(NN / 32, OUT_DIM / 32);
    transpose_kernel<<<gT, 256>>>(Wh, WhT);

    const int dyn_bytes = 2 * 2 * TILE_WORDS * 4;   // 139264
    cudaFuncSetAttribute(attn_kernel, cudaFuncAttributeMaxDynamicSharedMemorySize, dyn_bytes);
    dim3 gC(NN / 128, HEADS);
    attn_kernel<<<gC, 256, dyn_bytes>>>(A, WhT, slT, srT, MT, out);
}